// round 4
// baseline (speedup 1.0000x reference)
#include <cuda_runtime.h>
#include <math.h>

// ---------------------------------------------------------------------------
// TCVAE loss — single-launch, single-wave, latency-optimized.
//
// Algebra (ALPHA=BETA=GAMMA=1): pairwise logsumexp terms telescope away:
//   kl_loss = mean(log q(z|x)) - mean(log p(z))
// Remaining:
//   recon_loss = sum |x - recon| / (B*T)
//   kl_loss    = (1/B) * sum_{i,d} [ -0.5*((z-mu)^2*e^{-lv} + lv)
//                                    +0.5*( z^2*e^{-1}      + 1 ) ]
//
// vs round 3: 128 blocks x 1024 threads = exactly 1 CTA per SM (no 2-wave
// straggler), each thread owns a fixed work slice with all loads batched
// up-front (single memory round-trip depth). Ticket finalize, idempotent
// across graph replays.
// ---------------------------------------------------------------------------

#define GRID_BLOCKS 128
#define BLOCK_THREADS 1024
#define NTHREADS (GRID_BLOCKS * BLOCK_THREADS)   // 131072
#define NWARPS (BLOCK_THREADS / 32)              // 32

__device__ float2 g_partials[GRID_BLOCKS];
__device__ unsigned int g_ticket = 0;

__global__ void __launch_bounds__(BLOCK_THREADS) tcvae_fused_kernel(
    const float4* __restrict__ recon4,
    const float4* __restrict__ x4,
    const float4* __restrict__ mu4,
    const float4* __restrict__ lv4,
    const float4* __restrict__ z4,
    float* __restrict__ out,
    int n_bt4,                       // (B*T)/4 = 262144 = 2*NTHREADS
    int n_bd4,                       // (B*D)/4 = 16384
    int n_bt, int batch)
{
    const float INV_E = 0.36787944117144233f;  // e^{-1}

    int tid = blockIdx.x * BLOCK_THREADS + threadIdx.x;

    // ---- front-batch ALL independent loads (max MLP, one round trip) ----
    int i0 = tid;
    int i1 = tid + NTHREADS;
    float4 a0 = recon4[i0];
    float4 a1 = recon4[i1];
    float4 b0 = x4[i0];
    float4 b1 = x4[i1];

    bool has_kl = (tid < n_bd4);
    float4 m, l, s;
    if (has_kl) {
        m = mu4[tid];
        l = lv4[tid];
        s = z4[tid];
    }

    // ---- compute ----
    float racc = fabsf(b0.x - a0.x) + fabsf(b0.y - a0.y)
               + fabsf(b0.z - a0.z) + fabsf(b0.w - a0.w)
               + fabsf(b1.x - a1.x) + fabsf(b1.y - a1.y)
               + fabsf(b1.z - a1.z) + fabsf(b1.w - a1.w);

    float kacc = 0.0f;
    if (has_kl) {
        float t;
        t = s.x - m.x; kacc += -0.5f * (t*t*__expf(-l.x) + l.x) + 0.5f * (s.x*s.x*INV_E + 1.0f);
        t = s.y - m.y; kacc += -0.5f * (t*t*__expf(-l.y) + l.y) + 0.5f * (s.y*s.y*INV_E + 1.0f);
        t = s.z - m.z; kacc += -0.5f * (t*t*__expf(-l.z) + l.z) + 0.5f * (s.z*s.z*INV_E + 1.0f);
        t = s.w - m.w; kacc += -0.5f * (t*t*__expf(-l.w) + l.w) + 0.5f * (s.w*s.w*INV_E + 1.0f);
    }

    // ---- block reduction ----
    #pragma unroll
    for (int o = 16; o > 0; o >>= 1) {
        racc += __shfl_xor_sync(0xFFFFFFFFu, racc, o);
        kacc += __shfl_xor_sync(0xFFFFFFFFu, kacc, o);
    }

    __shared__ float sr[NWARPS];
    __shared__ float sk[NWARPS];
    int lane = threadIdx.x & 31;
    int warp = threadIdx.x >> 5;
    if (lane == 0) { sr[warp] = racc; sk[warp] = kacc; }
    __syncthreads();

    __shared__ bool is_last;
    if (warp == 0) {
        racc = sr[lane];
        kacc = sk[lane];
        #pragma unroll
        for (int o = 16; o > 0; o >>= 1) {
            racc += __shfl_xor_sync(0xFFFFFFFFu, racc, o);
            kacc += __shfl_xor_sync(0xFFFFFFFFu, kacc, o);
        }
        if (lane == 0) {
            g_partials[blockIdx.x] = make_float2(racc, kacc);
            // acq_rel: release orders the partial store before the ticket
            // bump; acquire covers the last block's partial reads.
            unsigned int t;
            asm volatile("atom.acq_rel.gpu.global.add.u32 %0, [%1], 1;"
                         : "=r"(t) : "l"(&g_ticket) : "memory");
            is_last = (t == (unsigned int)(GRID_BLOCKS - 1));
        }
    }
    __syncthreads();

    // ---- last-block finalize: 128 float2 = 1KB, one read, warp reduce ----
    if (is_last && warp < (GRID_BLOCKS / 32)) {
        int idx = warp * 32 + lane;
        float2 p = g_partials[idx];
        float r = p.x, k = p.y;
        #pragma unroll
        for (int o = 16; o > 0; o >>= 1) {
            r += __shfl_xor_sync(0xFFFFFFFFu, r, o);
            k += __shfl_xor_sync(0xFFFFFFFFu, k, o);
        }
        __shared__ double dr[GRID_BLOCKS / 32];
        __shared__ double dk[GRID_BLOCKS / 32];
        if (lane == 0) { dr[warp] = (double)r; dk[warp] = (double)k; }
        __syncthreads();
        if (threadIdx.x == 0) {
            double rs = 0.0, ks = 0.0;
            #pragma unroll
            for (int w = 0; w < GRID_BLOCKS / 32; w++) { rs += dr[w]; ks += dk[w]; }
            float recon_loss = (float)(rs / (double)n_bt);
            float kl_loss    = (float)(ks / (double)batch);
            out[0] = recon_loss + kl_loss;
            out[1] = recon_loss;
            out[2] = kl_loss;
            g_ticket = 0;  // reset for next graph replay (idempotent)
        }
    }
}

extern "C" void kernel_launch(void* const* d_in, const int* in_sizes, int n_in,
                              void* d_out, int out_size) {
    const float* recon   = (const float*)d_in[0];  // [B, T]
    const float* x       = (const float*)d_in[1];  // [B, T]
    const float* mu      = (const float*)d_in[2];  // [B, D]
    const float* log_var = (const float*)d_in[3];  // [B, D]
    const float* z       = (const float*)d_in[4];  // [B, D]
    // d_in[5] = dataset_size: unused (telescoping cancellation).

    int n_bt = in_sizes[0];          // B*T = 1048576
    int n_bd = in_sizes[2];          // B*D = 65536
    const int batch = 2048;          // B

    tcvae_fused_kernel<<<GRID_BLOCKS, BLOCK_THREADS>>>(
        (const float4*)recon, (const float4*)x,
        (const float4*)mu, (const float4*)log_var, (const float4*)z,
        (float*)d_out, n_bt / 4, n_bd / 4, n_bt, batch);
}